// round 2
// baseline (speedup 1.0000x reference)
#include <cuda_runtime.h>

#define NN 50000
#define EE 640000
#define QS 1024          // row stride of fused qkv/skip buffer

// ---- scratch (static device globals: allocation-free rule) ----
__device__ __align__(16) float g_buf[(size_t)NN * QS];   // [q|k|v|x_r] per node, 204.8MB
__device__ __align__(16) float g_h[(size_t)NN * 256];    // post-LN hidden, 51.2MB
__device__ int g_deg[NN];
__device__ int g_start[NN + 1];
__device__ int g_cur[NN];
__device__ int g_esrc[EE];

// ============================================================================
// Kernel 1: fused QKV+skip GEMM.  out[n, 1024] = x[n,64] @ [Wq|Wk|Wv|Wskip]^T + b
// 128x128 tile per block, K processed in two 32-chunks (32KB static smem).
// ============================================================================
__global__ __launch_bounds__(256) void gemm_qkvs(
    const float* __restrict__ x,
    const float* __restrict__ Wq, const float* __restrict__ bq,
    const float* __restrict__ Wk, const float* __restrict__ bk,
    const float* __restrict__ Wv, const float* __restrict__ bv,
    const float* __restrict__ Wsk, const float* __restrict__ bsk)
{
    __shared__ float Xs[32 * 128];   // [k][r]
    __shared__ float Wsh[32 * 128];  // [k][j]

    int t = threadIdx.x;
    int bx = blockIdx.x;             // col tile (0..7)
    int by = blockIdx.y;             // row tile (0..390)
    int c0 = bx * 128;
    int which = c0 >> 8;
    int dbase = c0 & 255;
    const float* W = (which == 0) ? Wq : (which == 1) ? Wk : (which == 2) ? Wv : Wsk;
    const float* B = (which == 0) ? bq : (which == 1) ? bk : (which == 2) ? bv : bsk;
    int row0 = by * 128;

    int tx = t & 15, ty = t >> 4;
    float acc[8][8];
#pragma unroll
    for (int i = 0; i < 8; i++)
#pragma unroll
        for (int j = 0; j < 8; j++) acc[i][j] = 0.f;

    for (int kc = 0; kc < 64; kc += 32) {
        __syncthreads();
        // load X chunk: 128 rows x 32 k  (units = 128*8 float4)
#pragma unroll
        for (int i = 0; i < 4; i++) {
            int u = t + i * 256;
            int r = u >> 3, kq = u & 7;
            int rg = row0 + r;
            float4 v = make_float4(0.f, 0.f, 0.f, 0.f);
            if (rg < NN) v = *(const float4*)(x + (size_t)rg * 64 + kc + kq * 4);
            Xs[(kq * 4 + 0) * 128 + r] = v.x;
            Xs[(kq * 4 + 1) * 128 + r] = v.y;
            Xs[(kq * 4 + 2) * 128 + r] = v.z;
            Xs[(kq * 4 + 3) * 128 + r] = v.w;
        }
        // load W chunk: 128 cols x 32 k
#pragma unroll
        for (int i = 0; i < 4; i++) {
            int u = t + i * 256;
            int j = u >> 3, kq = u & 7;
            float4 v = *(const float4*)(W + (size_t)(dbase + j) * 64 + kc + kq * 4);
            Wsh[(kq * 4 + 0) * 128 + j] = v.x;
            Wsh[(kq * 4 + 1) * 128 + j] = v.y;
            Wsh[(kq * 4 + 2) * 128 + j] = v.z;
            Wsh[(kq * 4 + 3) * 128 + j] = v.w;
        }
        __syncthreads();
#pragma unroll
        for (int k = 0; k < 32; k++) {
            float a[8], b[8];
            *(float4*)(a)     = *(const float4*)&Xs[k * 128 + ty * 8];
            *(float4*)(a + 4) = *(const float4*)&Xs[k * 128 + ty * 8 + 4];
            *(float4*)(b)     = *(const float4*)&Wsh[k * 128 + tx * 8];
            *(float4*)(b + 4) = *(const float4*)&Wsh[k * 128 + tx * 8 + 4];
#pragma unroll
            for (int i = 0; i < 8; i++)
#pragma unroll
                for (int j = 0; j < 8; j++) acc[i][j] += a[i] * b[j];
        }
    }
    // epilogue: + bias, store
    float bj[8];
#pragma unroll
    for (int j = 0; j < 8; j++) bj[j] = B[dbase + tx * 8 + j];
#pragma unroll
    for (int i = 0; i < 8; i++) {
        int rg = row0 + ty * 8 + i;
        if (rg >= NN) continue;
        float* op = g_buf + (size_t)rg * QS + c0 + tx * 8;
        float4 o0, o1;
        o0.x = acc[i][0] + bj[0]; o0.y = acc[i][1] + bj[1];
        o0.z = acc[i][2] + bj[2]; o0.w = acc[i][3] + bj[3];
        o1.x = acc[i][4] + bj[4]; o1.y = acc[i][5] + bj[5];
        o1.z = acc[i][6] + bj[6]; o1.w = acc[i][7] + bj[7];
        *(float4*)(op)     = o0;
        *(float4*)(op + 4) = o1;
    }
}

// ============================================================================
// CSR build: histogram -> exclusive scan (single block) -> scatter
// ============================================================================
__global__ __launch_bounds__(256) void hist_kernel(const int* __restrict__ ei)
{
    int e = blockIdx.x * 256 + threadIdx.x;
    if (e < EE) atomicAdd(&g_deg[ei[EE + e]], 1);
}

__global__ __launch_bounds__(1024) void scan_kernel()
{
    __shared__ int wsum[32];
    __shared__ int carryS;
    int t = threadIdx.x;
    int lane = t & 31, w = t >> 5;
    if (t == 0) carryS = 0;
    __syncthreads();
    for (int base = 0; base < NN; base += 1024) {
        int i = base + t;
        int v = (i < NN) ? g_deg[i] : 0;
        int xv = v;
#pragma unroll
        for (int off = 1; off < 32; off <<= 1) {
            int u = __shfl_up_sync(0xffffffffu, xv, off);
            if (lane >= off) xv += u;
        }
        if (lane == 31) wsum[w] = xv;
        __syncthreads();
        if (w == 0) {
            int y = wsum[lane];
#pragma unroll
            for (int off = 1; off < 32; off <<= 1) {
                int u = __shfl_up_sync(0xffffffffu, y, off);
                if (lane >= off) y += u;
            }
            wsum[lane] = y;
        }
        __syncthreads();
        int incl = xv + (w ? wsum[w - 1] : 0);
        int c = carryS;
        if (i < NN) g_start[i] = c + incl - v;
        __syncthreads();
        if (t == 0) carryS = c + wsum[31];
        __syncthreads();
    }
    if (t == 0) g_start[NN] = carryS;
}

__global__ __launch_bounds__(256) void scatter_kernel(const int* __restrict__ ei)
{
    int e = blockIdx.x * 256 + threadIdx.x;
    if (e < EE) {
        int d = ei[EE + e];
        int s = ei[e];
        int pos = g_start[d] + atomicAdd(&g_cur[d], 1);
        g_esrc[pos] = s;
    }
}

// ============================================================================
// Kernel 3: warp-per-dst online-softmax attention + aggregate + beta-gate + LN
// Lane l owns channels [8l, 8l+8); head = l/8; head-dot via width-8 shfl_xor.
// ============================================================================
__global__ __launch_bounds__(256) void attn_kernel(
    const float* __restrict__ Wbeta,
    const float* __restrict__ lng, const float* __restrict__ lnb)
{
    __shared__ float sWb[768];
    __shared__ float sg[256], sb[256];
    int t = threadIdx.x;
    for (int i = t; i < 768; i += 256) sWb[i] = Wbeta[i];
    if (t < 256) { sg[t] = lng[t]; sb[t] = lnb[t]; }
    __syncthreads();

    int warp = t >> 5, lane = t & 31;
    int node = blockIdx.x * 8 + warp;
    if (node >= NN) return;

    int c0 = lane * 8;
    const float* qp = g_buf + (size_t)node * QS + c0;
    float q[8];
    *(float4*)(q)     = *(const float4*)(qp);
    *(float4*)(q + 4) = *(const float4*)(qp + 4);
#pragma unroll
    for (int u = 0; u < 8; u++) q[u] *= 0.125f;   // 1/sqrt(64)

    float m = -1e30f, ssum = 0.f;
    float acc[8];
#pragma unroll
    for (int u = 0; u < 8; u++) acc[u] = 0.f;

    int e0 = g_start[node], e1 = g_start[node + 1];
    for (int e = e0; e < e1; e++) {
        int src = g_esrc[e];
        const float* kp = g_buf + (size_t)src * QS + 256 + c0;
        float4 ka = *(const float4*)(kp);
        float4 kb = *(const float4*)(kp + 4);
        float p = q[0] * ka.x + q[1] * ka.y + q[2] * ka.z + q[3] * ka.w
                + q[4] * kb.x + q[5] * kb.y + q[6] * kb.z + q[7] * kb.w;
        // reduce within this lane's 8-lane head group
        p += __shfl_xor_sync(0xffffffffu, p, 1, 8);
        p += __shfl_xor_sync(0xffffffffu, p, 2, 8);
        p += __shfl_xor_sync(0xffffffffu, p, 4, 8);
        float mn = fmaxf(m, p);
        float sc = __expf(m - mn);
        float wgt = __expf(p - mn);
        m = mn;
        const float* vp = g_buf + (size_t)src * QS + 512 + c0;
        float4 va = *(const float4*)(vp);
        float4 vb = *(const float4*)(vp + 4);
        ssum = ssum * sc + wgt;
        acc[0] = acc[0] * sc + wgt * va.x;
        acc[1] = acc[1] * sc + wgt * va.y;
        acc[2] = acc[2] * sc + wgt * va.z;
        acc[3] = acc[3] * sc + wgt * va.w;
        acc[4] = acc[4] * sc + wgt * vb.x;
        acc[5] = acc[5] * sc + wgt * vb.y;
        acc[6] = acc[6] * sc + wgt * vb.z;
        acc[7] = acc[7] * sc + wgt * vb.w;
    }
    float inv = 1.f / (ssum + 1e-16f);
    float outv[8];
#pragma unroll
    for (int u = 0; u < 8; u++) outv[u] = acc[u] * inv;

    const float* xp = g_buf + (size_t)node * QS + 768 + c0;
    float xr[8];
    *(float4*)(xr)     = *(const float4*)(xp);
    *(float4*)(xr + 4) = *(const float4*)(xp + 4);

    // beta = sigmoid( [out, x_r, out - x_r] . Wbeta )
    float part = 0.f;
#pragma unroll
    for (int u = 0; u < 8; u++) {
        int c = c0 + u;
        part += outv[u] * sWb[c] + xr[u] * sWb[256 + c] + (outv[u] - xr[u]) * sWb[512 + c];
    }
#pragma unroll
    for (int off = 16; off > 0; off >>= 1)
        part += __shfl_xor_sync(0xffffffffu, part, off);
    float beta = 1.f / (1.f + __expf(-part));

    float h[8], sum = 0.f, sq = 0.f;
#pragma unroll
    for (int u = 0; u < 8; u++) {
        h[u] = beta * xr[u] + (1.f - beta) * outv[u];
        sum += h[u];
        sq += h[u] * h[u];
    }
#pragma unroll
    for (int off = 16; off > 0; off >>= 1) {
        sum += __shfl_xor_sync(0xffffffffu, sum, off);
        sq  += __shfl_xor_sync(0xffffffffu, sq, off);
    }
    float mu = sum * (1.f / 256.f);
    float var = sq * (1.f / 256.f) - mu * mu;
    float rstd = rsqrtf(var + 1e-5f);

    float o[8];
#pragma unroll
    for (int u = 0; u < 8; u++) {
        int c = c0 + u;
        o[u] = (h[u] - mu) * rstd * sg[c] + sb[c];
    }
    float* hp = g_h + (size_t)node * 256 + c0;
    *(float4*)(hp)     = *(const float4*)(o);
    *(float4*)(hp + 4) = *(const float4*)(o + 4);
}

// ============================================================================
// Kernel 4: proj GEMM + bias + residual + ReLU.  out[n,64] = relu(h@Wp^T + bp + x)
// 128-row tile, all 64 cols, K=256 in chunks of 32.
// ============================================================================
__global__ __launch_bounds__(256) void gemm_proj(
    const float* __restrict__ x,
    const float* __restrict__ Wp, const float* __restrict__ bp,
    float* __restrict__ out)
{
    __shared__ float Hs[32 * 128];  // [k][r]
    __shared__ float Ws[32 * 64];   // [k][j]
    int t = threadIdx.x;
    int by = blockIdx.x;
    int row0 = by * 128;
    int tx = t & 15, ty = t >> 4;

    float acc[8][4];
#pragma unroll
    for (int i = 0; i < 8; i++)
#pragma unroll
        for (int j = 0; j < 4; j++) acc[i][j] = 0.f;

    for (int kc = 0; kc < 256; kc += 32) {
        __syncthreads();
#pragma unroll
        for (int i = 0; i < 4; i++) {
            int u = t + i * 256;
            int r = u >> 3, kq = u & 7;
            int rg = row0 + r;
            float4 v = make_float4(0.f, 0.f, 0.f, 0.f);
            if (rg < NN) v = *(const float4*)(g_h + (size_t)rg * 256 + kc + kq * 4);
            Hs[(kq * 4 + 0) * 128 + r] = v.x;
            Hs[(kq * 4 + 1) * 128 + r] = v.y;
            Hs[(kq * 4 + 2) * 128 + r] = v.z;
            Hs[(kq * 4 + 3) * 128 + r] = v.w;
        }
#pragma unroll
        for (int i = 0; i < 2; i++) {
            int u = t + i * 256;
            int j = u >> 3, kq = u & 7;
            float4 v = *(const float4*)(Wp + (size_t)j * 256 + kc + kq * 4);
            Ws[(kq * 4 + 0) * 64 + j] = v.x;
            Ws[(kq * 4 + 1) * 64 + j] = v.y;
            Ws[(kq * 4 + 2) * 64 + j] = v.z;
            Ws[(kq * 4 + 3) * 64 + j] = v.w;
        }
        __syncthreads();
#pragma unroll
        for (int k = 0; k < 32; k++) {
            float a[8];
            *(float4*)(a)     = *(const float4*)&Hs[k * 128 + ty * 8];
            *(float4*)(a + 4) = *(const float4*)&Hs[k * 128 + ty * 8 + 4];
            float4 b4 = *(const float4*)&Ws[k * 64 + tx * 4];
            float b[4] = { b4.x, b4.y, b4.z, b4.w };
#pragma unroll
            for (int i = 0; i < 8; i++)
#pragma unroll
                for (int j = 0; j < 4; j++) acc[i][j] += a[i] * b[j];
        }
    }
    float4 bias = *(const float4*)(bp + tx * 4);
#pragma unroll
    for (int i = 0; i < 8; i++) {
        int rg = row0 + ty * 8 + i;
        if (rg >= NN) continue;
        float4 xv = *(const float4*)(x + (size_t)rg * 64 + tx * 4);
        float4 o;
        o.x = fmaxf(acc[i][0] + bias.x + xv.x, 0.f);
        o.y = fmaxf(acc[i][1] + bias.y + xv.y, 0.f);
        o.z = fmaxf(acc[i][2] + bias.z + xv.z, 0.f);
        o.w = fmaxf(acc[i][3] + bias.w + xv.w, 0.f);
        *(float4*)(out + (size_t)rg * 64 + tx * 4) = o;
    }
}

// ============================================================================
extern "C" void kernel_launch(void* const* d_in, const int* in_sizes, int n_in,
                              void* d_out, int out_size)
{
    const float* x     = (const float*)d_in[0];
    const int*   ei    = (const int*)d_in[1];
    const float* Wq    = (const float*)d_in[2];
    const float* bq    = (const float*)d_in[3];
    const float* Wk    = (const float*)d_in[4];
    const float* bk    = (const float*)d_in[5];
    const float* Wv    = (const float*)d_in[6];
    const float* bv    = (const float*)d_in[7];
    const float* Wsk   = (const float*)d_in[8];
    const float* bsk   = (const float*)d_in[9];
    const float* Wbeta = (const float*)d_in[10];
    const float* lng   = (const float*)d_in[11];
    const float* lnb   = (const float*)d_in[12];
    const float* Wp    = (const float*)d_in[13];
    const float* bp    = (const float*)d_in[14];
    float* out = (float*)d_out;

    void *degp = nullptr, *curp = nullptr;
    cudaGetSymbolAddress(&degp, g_deg);
    cudaGetSymbolAddress(&curp, g_cur);
    cudaMemsetAsync(degp, 0, NN * sizeof(int));
    cudaMemsetAsync(curp, 0, NN * sizeof(int));

    gemm_qkvs<<<dim3(8, 391), 256>>>(x, Wq, bq, Wk, bk, Wv, bv, Wsk, bsk);
    hist_kernel<<<2500, 256>>>(ei);
    scan_kernel<<<1, 1024>>>();
    scatter_kernel<<<2500, 256>>>(ei);
    attn_kernel<<<6250, 256>>>(Wbeta, lng, lnb);
    gemm_proj<<<391, 256>>>(x, Wp, bp, out);
}

// round 3
// speedup vs baseline: 1.0144x; 1.0144x over previous
#include <cuda_runtime.h>

#define NN 50000
#define EE 640000
#define QS 1024          // row stride of fused qkv/skip buffer

// ---- scratch (static device globals: allocation-free rule) ----
__device__ __align__(16) float g_buf[(size_t)NN * QS];   // [q|k|v|x_r] per node, 204.8MB
__device__ __align__(16) float g_h[(size_t)NN * 256];    // post-LN hidden, 51.2MB
__device__ int g_deg[NN];
__device__ int g_start[NN + 1];
__device__ int g_cur[NN];
__device__ int g_esrc[EE];

// ---- packed f32x2 helpers (Blackwell FFMA2: 2x fp32 math per fma-pipe slot) ----
#define PACK2(p, lo, hi)   asm("mov.b64 %0, {%1,%2};" : "=l"(p) : "f"(lo), "f"(hi))
#define BCAST2(p, v)       asm("mov.b64 %0, {%1,%1};" : "=l"(p) : "f"(v))
#define UNPACK2(lo, hi, p) asm("mov.b64 {%0,%1}, %2;" : "=f"(lo), "=f"(hi) : "l"(p))
#define FMA2(d, a, b, c)   asm("fma.rn.f32x2 %0, %1, %2, %3;" : "=l"(d) : "l"(a), "l"(b), "l"(c))

// ============================================================================
// Kernel 1: fused QKV+skip GEMM.  out[n, 1024] = x[n,64] @ [Wq|Wk|Wv|Wskip]^T + b
// 128x128 tile per block, K in two 32-chunks; inner product on fma.rn.f32x2.
// ============================================================================
__global__ __launch_bounds__(256) void gemm_qkvs(
    const float* __restrict__ x,
    const float* __restrict__ Wq, const float* __restrict__ bq,
    const float* __restrict__ Wk, const float* __restrict__ bk,
    const float* __restrict__ Wv, const float* __restrict__ bv,
    const float* __restrict__ Wsk, const float* __restrict__ bsk)
{
    __shared__ float Xs[32 * 128];   // [k][r]
    __shared__ float Wsh[32 * 128];  // [k][j]

    int t = threadIdx.x;
    int bx = blockIdx.x;             // col tile (0..7)
    int by = blockIdx.y;             // row tile (0..390)
    int c0 = bx * 128;
    int which = c0 >> 8;
    int dbase = c0 & 255;
    const float* W = (which == 0) ? Wq : (which == 1) ? Wk : (which == 2) ? Wv : Wsk;
    const float* B = (which == 0) ? bq : (which == 1) ? bk : (which == 2) ? bv : bsk;
    int row0 = by * 128;

    int tx = t & 15, ty = t >> 4;
    unsigned long long acc[8][4];    // 8 rows x 4 col-pairs
#pragma unroll
    for (int i = 0; i < 8; i++)
#pragma unroll
        for (int j = 0; j < 4; j++) acc[i][j] = 0ull;

    for (int kc = 0; kc < 64; kc += 32) {
        __syncthreads();
        // load X chunk: 128 rows x 32 k
#pragma unroll
        for (int i = 0; i < 4; i++) {
            int u = t + i * 256;
            int r = u >> 3, kq = u & 7;
            int rg = row0 + r;
            float4 v = make_float4(0.f, 0.f, 0.f, 0.f);
            if (rg < NN) v = *(const float4*)(x + (size_t)rg * 64 + kc + kq * 4);
            Xs[(kq * 4 + 0) * 128 + r] = v.x;
            Xs[(kq * 4 + 1) * 128 + r] = v.y;
            Xs[(kq * 4 + 2) * 128 + r] = v.z;
            Xs[(kq * 4 + 3) * 128 + r] = v.w;
        }
        // load W chunk: 128 cols x 32 k
#pragma unroll
        for (int i = 0; i < 4; i++) {
            int u = t + i * 256;
            int j = u >> 3, kq = u & 7;
            float4 v = *(const float4*)(W + (size_t)(dbase + j) * 64 + kc + kq * 4);
            Wsh[(kq * 4 + 0) * 128 + j] = v.x;
            Wsh[(kq * 4 + 1) * 128 + j] = v.y;
            Wsh[(kq * 4 + 2) * 128 + j] = v.z;
            Wsh[(kq * 4 + 3) * 128 + j] = v.w;
        }
        __syncthreads();
#pragma unroll
        for (int k = 0; k < 32; k++) {
            float a[8];
            *(float4*)(a)     = *(const float4*)&Xs[k * 128 + ty * 8];
            *(float4*)(a + 4) = *(const float4*)&Xs[k * 128 + ty * 8 + 4];
            float4 b0 = *(const float4*)&Wsh[k * 128 + tx * 8];
            float4 b1 = *(const float4*)&Wsh[k * 128 + tx * 8 + 4];
            unsigned long long bp[4];
            PACK2(bp[0], b0.x, b0.y);
            PACK2(bp[1], b0.z, b0.w);
            PACK2(bp[2], b1.x, b1.y);
            PACK2(bp[3], b1.z, b1.w);
#pragma unroll
            for (int i = 0; i < 8; i++) {
                unsigned long long ap;
                BCAST2(ap, a[i]);
#pragma unroll
                for (int j = 0; j < 4; j++) FMA2(acc[i][j], ap, bp[j], acc[i][j]);
            }
        }
    }
    // epilogue: + bias, store
    float bj[8];
#pragma unroll
    for (int j = 0; j < 8; j++) bj[j] = B[dbase + tx * 8 + j];
#pragma unroll
    for (int i = 0; i < 8; i++) {
        int rg = row0 + ty * 8 + i;
        if (rg >= NN) continue;
        float* op = g_buf + (size_t)rg * QS + c0 + tx * 8;
        float c[8];
#pragma unroll
        for (int j = 0; j < 4; j++) UNPACK2(c[2 * j], c[2 * j + 1], acc[i][j]);
        float4 o0, o1;
        o0.x = c[0] + bj[0]; o0.y = c[1] + bj[1];
        o0.z = c[2] + bj[2]; o0.w = c[3] + bj[3];
        o1.x = c[4] + bj[4]; o1.y = c[5] + bj[5];
        o1.z = c[6] + bj[6]; o1.w = c[7] + bj[7];
        *(float4*)(op)     = o0;
        *(float4*)(op + 4) = o1;
    }
}

// ============================================================================
// CSR build: histogram -> exclusive scan (single block) -> scatter
// ============================================================================
__global__ __launch_bounds__(256) void hist_kernel(const int* __restrict__ ei)
{
    int e = blockIdx.x * 256 + threadIdx.x;
    if (e < EE) atomicAdd(&g_deg[ei[EE + e]], 1);
}

__global__ __launch_bounds__(1024) void scan_kernel()
{
    __shared__ int wsum[32];
    __shared__ int carryS;
    int t = threadIdx.x;
    int lane = t & 31, w = t >> 5;
    if (t == 0) carryS = 0;
    __syncthreads();
    for (int base = 0; base < NN; base += 1024) {
        int i = base + t;
        int v = (i < NN) ? g_deg[i] : 0;
        int xv = v;
#pragma unroll
        for (int off = 1; off < 32; off <<= 1) {
            int u = __shfl_up_sync(0xffffffffu, xv, off);
            if (lane >= off) xv += u;
        }
        if (lane == 31) wsum[w] = xv;
        __syncthreads();
        if (w == 0) {
            int y = wsum[lane];
#pragma unroll
            for (int off = 1; off < 32; off <<= 1) {
                int u = __shfl_up_sync(0xffffffffu, y, off);
                if (lane >= off) y += u;
            }
            wsum[lane] = y;
        }
        __syncthreads();
        int incl = xv + (w ? wsum[w - 1] : 0);
        int c = carryS;
        if (i < NN) g_start[i] = c + incl - v;
        __syncthreads();
        if (t == 0) carryS = c + wsum[31];
        __syncthreads();
    }
    if (t == 0) g_start[NN] = carryS;
}

__global__ __launch_bounds__(256) void scatter_kernel(const int* __restrict__ ei)
{
    int e = blockIdx.x * 256 + threadIdx.x;
    if (e < EE) {
        int d = ei[EE + e];
        int s = ei[e];
        int pos = g_start[d] + atomicAdd(&g_cur[d], 1);
        g_esrc[pos] = s;
    }
}

// ============================================================================
// Kernel 3: warp-per-dst online-softmax attention + aggregate + beta-gate + LN
// Lane l owns channels [8l, 8l+8); head = l/8; head-dot via width-8 shfl_xor.
// All 4 gather LDG.128s + next-edge src prefetch issued ahead of the shfl chain.
// ============================================================================
__global__ __launch_bounds__(256) void attn_kernel(
    const float* __restrict__ Wbeta,
    const float* __restrict__ lng, const float* __restrict__ lnb)
{
    __shared__ float sWb[768];
    __shared__ float sg[256], sb[256];
    int t = threadIdx.x;
    for (int i = t; i < 768; i += 256) sWb[i] = Wbeta[i];
    if (t < 256) { sg[t] = lng[t]; sb[t] = lnb[t]; }
    __syncthreads();

    int warp = t >> 5, lane = t & 31;
    int node = blockIdx.x * 8 + warp;
    if (node >= NN) return;

    int c0 = lane * 8;
    const float* qp = g_buf + (size_t)node * QS + c0;
    float q[8];
    *(float4*)(q)     = *(const float4*)(qp);
    *(float4*)(q + 4) = *(const float4*)(qp + 4);
#pragma unroll
    for (int u = 0; u < 8; u++) q[u] *= 0.125f;   // 1/sqrt(64)

    float m = -1e30f, ssum = 0.f;
    float acc[8];
#pragma unroll
    for (int u = 0; u < 8; u++) acc[u] = 0.f;

    int e0 = g_start[node], e1 = g_start[node + 1];
    int src = (e0 < e1) ? g_esrc[e0] : 0;
    for (int e = e0; e < e1; e++) {
        // issue all gathers for this edge + next src before the reduce chain
        const float* kp = g_buf + (size_t)src * QS + 256 + c0;
        float4 ka = *(const float4*)(kp);
        float4 kb = *(const float4*)(kp + 4);
        float4 va = *(const float4*)(kp + 256);
        float4 vb = *(const float4*)(kp + 260);
        int nsrc = (e + 1 < e1) ? g_esrc[e + 1] : 0;

        float p = q[0] * ka.x + q[1] * ka.y + q[2] * ka.z + q[3] * ka.w
                + q[4] * kb.x + q[5] * kb.y + q[6] * kb.z + q[7] * kb.w;
        // reduce within this lane's 8-lane head group
        p += __shfl_xor_sync(0xffffffffu, p, 1, 8);
        p += __shfl_xor_sync(0xffffffffu, p, 2, 8);
        p += __shfl_xor_sync(0xffffffffu, p, 4, 8);
        float mn = fmaxf(m, p);
        float sc = __expf(m - mn);
        float wgt = __expf(p - mn);
        m = mn;
        ssum = ssum * sc + wgt;
        acc[0] = acc[0] * sc + wgt * va.x;
        acc[1] = acc[1] * sc + wgt * va.y;
        acc[2] = acc[2] * sc + wgt * va.z;
        acc[3] = acc[3] * sc + wgt * va.w;
        acc[4] = acc[4] * sc + wgt * vb.x;
        acc[5] = acc[5] * sc + wgt * vb.y;
        acc[6] = acc[6] * sc + wgt * vb.z;
        acc[7] = acc[7] * sc + wgt * vb.w;
        src = nsrc;
    }
    float inv = 1.f / (ssum + 1e-16f);
    float outv[8];
#pragma unroll
    for (int u = 0; u < 8; u++) outv[u] = acc[u] * inv;

    const float* xp = g_buf + (size_t)node * QS + 768 + c0;
    float xr[8];
    *(float4*)(xr)     = *(const float4*)(xp);
    *(float4*)(xr + 4) = *(const float4*)(xp + 4);

    // beta = sigmoid( [out, x_r, out - x_r] . Wbeta )
    float part = 0.f;
#pragma unroll
    for (int u = 0; u < 8; u++) {
        int c = c0 + u;
        part += outv[u] * sWb[c] + xr[u] * sWb[256 + c] + (outv[u] - xr[u]) * sWb[512 + c];
    }
#pragma unroll
    for (int off = 16; off > 0; off >>= 1)
        part += __shfl_xor_sync(0xffffffffu, part, off);
    float beta = 1.f / (1.f + __expf(-part));

    float h[8], sum = 0.f, sq = 0.f;
#pragma unroll
    for (int u = 0; u < 8; u++) {
        h[u] = beta * xr[u] + (1.f - beta) * outv[u];
        sum += h[u];
        sq += h[u] * h[u];
    }
#pragma unroll
    for (int off = 16; off > 0; off >>= 1) {
        sum += __shfl_xor_sync(0xffffffffu, sum, off);
        sq  += __shfl_xor_sync(0xffffffffu, sq, off);
    }
    float mu = sum * (1.f / 256.f);
    float var = sq * (1.f / 256.f) - mu * mu;
    float rstd = rsqrtf(var + 1e-5f);

    float o[8];
#pragma unroll
    for (int u = 0; u < 8; u++) {
        int c = c0 + u;
        o[u] = (h[u] - mu) * rstd * sg[c] + sb[c];
    }
    float* hp = g_h + (size_t)node * 256 + c0;
    *(float4*)(hp)     = *(const float4*)(o);
    *(float4*)(hp + 4) = *(const float4*)(o + 4);
}

// ============================================================================
// Kernel 4: proj GEMM + bias + residual + ReLU.  out[n,64] = relu(h@Wp^T + bp + x)
// 128-row tile, all 64 cols, K=256 in chunks of 32; FFMA2 inner product.
// ============================================================================
__global__ __launch_bounds__(256) void gemm_proj(
    const float* __restrict__ x,
    const float* __restrict__ Wp, const float* __restrict__ bp,
    float* __restrict__ out)
{
    __shared__ float Hs[32 * 128];  // [k][r]
    __shared__ float Ws[32 * 64];   // [k][j]
    int t = threadIdx.x;
    int by = blockIdx.x;
    int row0 = by * 128;
    int tx = t & 15, ty = t >> 4;

    unsigned long long acc[8][2];   // 8 rows x 2 col-pairs
#pragma unroll
    for (int i = 0; i < 8; i++)
#pragma unroll
        for (int j = 0; j < 2; j++) acc[i][j] = 0ull;

    for (int kc = 0; kc < 256; kc += 32) {
        __syncthreads();
#pragma unroll
        for (int i = 0; i < 4; i++) {
            int u = t + i * 256;
            int r = u >> 3, kq = u & 7;
            int rg = row0 + r;
            float4 v = make_float4(0.f, 0.f, 0.f, 0.f);
            if (rg < NN) v = *(const float4*)(g_h + (size_t)rg * 256 + kc + kq * 4);
            Hs[(kq * 4 + 0) * 128 + r] = v.x;
            Hs[(kq * 4 + 1) * 128 + r] = v.y;
            Hs[(kq * 4 + 2) * 128 + r] = v.z;
            Hs[(kq * 4 + 3) * 128 + r] = v.w;
        }
#pragma unroll
        for (int i = 0; i < 2; i++) {
            int u = t + i * 256;
            int j = u >> 3, kq = u & 7;
            float4 v = *(const float4*)(Wp + (size_t)j * 256 + kc + kq * 4);
            Ws[(kq * 4 + 0) * 64 + j] = v.x;
            Ws[(kq * 4 + 1) * 64 + j] = v.y;
            Ws[(kq * 4 + 2) * 64 + j] = v.z;
            Ws[(kq * 4 + 3) * 64 + j] = v.w;
        }
        __syncthreads();
#pragma unroll
        for (int k = 0; k < 32; k++) {
            float a[8];
            *(float4*)(a)     = *(const float4*)&Hs[k * 128 + ty * 8];
            *(float4*)(a + 4) = *(const float4*)&Hs[k * 128 + ty * 8 + 4];
            float4 b4 = *(const float4*)&Ws[k * 64 + tx * 4];
            unsigned long long bpair[2];
            PACK2(bpair[0], b4.x, b4.y);
            PACK2(bpair[1], b4.z, b4.w);
#pragma unroll
            for (int i = 0; i < 8; i++) {
                unsigned long long ap;
                BCAST2(ap, a[i]);
                FMA2(acc[i][0], ap, bpair[0], acc[i][0]);
                FMA2(acc[i][1], ap, bpair[1], acc[i][1]);
            }
        }
    }
    float4 bias = *(const float4*)(bp + tx * 4);
#pragma unroll
    for (int i = 0; i < 8; i++) {
        int rg = row0 + ty * 8 + i;
        if (rg >= NN) continue;
        float4 xv = *(const float4*)(x + (size_t)rg * 64 + tx * 4);
        float c[4];
        UNPACK2(c[0], c[1], acc[i][0]);
        UNPACK2(c[2], c[3], acc[i][1]);
        float4 o;
        o.x = fmaxf(c[0] + bias.x + xv.x, 0.f);
        o.y = fmaxf(c[1] + bias.y + xv.y, 0.f);
        o.z = fmaxf(c[2] + bias.z + xv.z, 0.f);
        o.w = fmaxf(c[3] + bias.w + xv.w, 0.f);
        *(float4*)(out + (size_t)rg * 64 + tx * 4) = o;
    }
}

// ============================================================================
extern "C" void kernel_launch(void* const* d_in, const int* in_sizes, int n_in,
                              void* d_out, int out_size)
{
    const float* x     = (const float*)d_in[0];
    const int*   ei    = (const int*)d_in[1];
    const float* Wq    = (const float*)d_in[2];
    const float* bq    = (const float*)d_in[3];
    const float* Wk    = (const float*)d_in[4];
    const float* bk    = (const float*)d_in[5];
    const float* Wv    = (const float*)d_in[6];
    const float* bv    = (const float*)d_in[7];
    const float* Wsk   = (const float*)d_in[8];
    const float* bsk   = (const float*)d_in[9];
    const float* Wbeta = (const float*)d_in[10];
    const float* lng   = (const float*)d_in[11];
    const float* lnb   = (const float*)d_in[12];
    const float* Wp    = (const float*)d_in[13];
    const float* bp    = (const float*)d_in[14];
    float* out = (float*)d_out;

    void *degp = nullptr, *curp = nullptr;
    cudaGetSymbolAddress(&degp, g_deg);
    cudaGetSymbolAddress(&curp, g_cur);
    cudaMemsetAsync(degp, 0, NN * sizeof(int));
    cudaMemsetAsync(curp, 0, NN * sizeof(int));

    gemm_qkvs<<<dim3(8, 391), 256>>>(x, Wq, bq, Wk, bk, Wv, bv, Wsk, bsk);
    hist_kernel<<<2500, 256>>>(ei);
    scan_kernel<<<1, 1024>>>();
    scatter_kernel<<<2500, 256>>>(ei);
    attn_kernel<<<6250, 256>>>(Wbeta, lng, lnb);
    gemm_proj<<<391, 256>>>(x, Wp, bp, out);
}